// round 6
// baseline (speedup 1.0000x reference)
#include <cuda_runtime.h>
#include <math.h>

#define B_   4
#define L_   2048
#define DX_  1024
#define H_   16
#define DK_  64
#define HD_  1024      // H*DK
#define EPS_ 1e-5f

// ---------------- scratch (device globals; no allocation allowed) ----------------
__device__ float g_Qs[(size_t)B_ * L_ * HD_];
__device__ float g_Ks[(size_t)B_ * L_ * HD_];
__device__ float g_Vs[(size_t)B_ * L_ * HD_];
__device__ float g_AO[(size_t)B_ * L_ * HD_];
__device__ float g_X [(size_t)B_ * L_ * DX_];
__device__ float2 g_part [(size_t)B_ * H_ * 16 * L_];  // per (bh, k-tile, row): (max, expsum)
__device__ float2 g_rowMS[(size_t)B_ * H_ * L_];       // per (bh, row): (max, 1/sum)

// ---------------- cp.async / mma helpers -----------------------------------------
__device__ __forceinline__ void cp16(void* s, const void* g) {
    unsigned a = (unsigned)__cvta_generic_to_shared(s);
    asm volatile("cp.async.cg.shared.global [%0], [%1], 16;" :: "r"(a), "l"(g));
}
__device__ __forceinline__ void cpcommit() {
    asm volatile("cp.async.commit_group;" ::: "memory");
}
__device__ __forceinline__ void cpwait0() {
    asm volatile("cp.async.wait_group 0;" ::: "memory");
}

// raw fp32 bits fed as tf32 (hw truncation)
__device__ __forceinline__ void mma8(float* d, const unsigned* a, const unsigned* b) {
    asm volatile(
        "mma.sync.aligned.m16n8k8.row.col.f32.tf32.tf32.f32 "
        "{%0,%1,%2,%3},{%4,%5,%6,%7},{%8,%9},{%0,%1,%2,%3};"
        : "+f"(d[0]), "+f"(d[1]), "+f"(d[2]), "+f"(d[3])
        : "r"(a[0]), "r"(a[1]), "r"(a[2]), "r"(a[3]), "r"(b[0]), "r"(b[1]));
}

// ================= TF32 SGEMM: C[M,N] = A[M,K] @ B[K,N] + bias ===================
__global__ __launch_bounds__(256, 2) void sgemm_tf32(
    const float* __restrict__ A, const float* __restrict__ Bm,
    const float* __restrict__ bias, float* __restrict__ C,
    int M, int N, int K)
{
    __shared__ unsigned As[2][128][20];
    __shared__ unsigned Bs[2][16][136];
    const int tid  = threadIdx.x;
    const int lane = tid & 31, warp = tid >> 5;
    const int wr = warp >> 1, wc = warp & 1;
    const int gm = lane >> 2, kq = lane & 3;

    const float* Ab = A  + (size_t)(blockIdx.y * 128) * K;
    const float* Bb = Bm + blockIdx.x * 128;
    const int arow = tid >> 1,  acol = (tid & 1) * 8;
    const int brow = tid >> 4,  bcol = (tid & 15) * 8;

    float acc[2][8][4];
#pragma unroll
    for (int i = 0; i < 2; i++)
#pragma unroll
        for (int j = 0; j < 8; j++)
#pragma unroll
            for (int r = 0; r < 4; r++) acc[i][j][r] = 0.f;

    auto load = [&](int buf, int k0) {
        cp16(&As[buf][arow][acol],     Ab + (size_t)arow * K + k0 + acol);
        cp16(&As[buf][arow][acol + 4], Ab + (size_t)arow * K + k0 + acol + 4);
        cp16(&Bs[buf][brow][bcol],     Bb + (size_t)(k0 + brow) * N + bcol);
        cp16(&Bs[buf][brow][bcol + 4], Bb + (size_t)(k0 + brow) * N + bcol + 4);
    };

    load(0, 0); cpcommit();
    int buf = 0;
    for (int k0 = 0; k0 < K; k0 += 16) {
        cpwait0();
        __syncthreads();
        if (k0 + 16 < K) { load(buf ^ 1, k0 + 16); cpcommit(); }
#pragma unroll
        for (int kk = 0; kk < 16; kk += 8) {
            unsigned af[2][4], bf[8][2];
#pragma unroll
            for (int i = 0; i < 2; i++) {
                const int mb = wr * 32 + i * 16;
                af[i][0] = As[buf][mb + gm    ][kk + kq];
                af[i][1] = As[buf][mb + gm + 8][kk + kq];
                af[i][2] = As[buf][mb + gm    ][kk + kq + 4];
                af[i][3] = As[buf][mb + gm + 8][kk + kq + 4];
            }
#pragma unroll
            for (int j = 0; j < 8; j++) {
                const int nb = wc * 64 + j * 8;
                bf[j][0] = Bs[buf][kk + kq    ][nb + gm];
                bf[j][1] = Bs[buf][kk + kq + 4][nb + gm];
            }
#pragma unroll
            for (int i = 0; i < 2; i++)
#pragma unroll
                for (int j = 0; j < 8; j++) mma8(acc[i][j], af[i], bf[j]);
        }
        __syncthreads();
        buf ^= 1;
    }

#pragma unroll
    for (int i = 0; i < 2; i++)
#pragma unroll
        for (int j = 0; j < 8; j++) {
            const int row = blockIdx.y * 128 + wr * 32 + i * 16 + gm;
            const int col = blockIdx.x * 128 + wc * 64 + j * 8 + kq * 2;
            float2 bv = *(const float2*)(bias + col);
            float2 o0, o1;
            o0.x = acc[i][j][0] + bv.x; o0.y = acc[i][j][1] + bv.y;
            o1.x = acc[i][j][2] + bv.x; o1.y = acc[i][j][3] + bv.y;
            *(float2*)(C + (size_t)row * N + col)       = o0;
            *(float2*)(C + (size_t)(row + 8) * N + col) = o1;
        }
}

// ============ scores: S = (Qh @ Kh^T)/8 masked; writes raw S + per-tile row stats =
#define SCS 68
__global__ __launch_bounds__(256, 2) void scores_tf32(
    const float* __restrict__ Qs, const float* __restrict__ Ks,
    const unsigned char* __restrict__ mask, float* __restrict__ att,
    float2* __restrict__ part)
{
    extern __shared__ unsigned sm[];
    unsigned (*Qt)[SCS] = (unsigned(*)[SCS])sm;
    unsigned (*Kt)[SCS] = (unsigned(*)[SCS])(sm + 128 * SCS);
    __shared__ float pm[2][128], ps[2][128];

    const int tid  = threadIdx.x;
    const int lane = tid & 31, warp = tid >> 5;
    const int wr = warp >> 1, wc = warp & 1;
    const int gm = lane >> 2, kq = lane & 3;
    const int bh = blockIdx.z;
    const int b = bh >> 4, h = bh & 15;
    const int q0 = blockIdx.y * 128, n0 = blockIdx.x * 128;

    const float* Qb = Qs + (size_t)b * L_ * HD_ + (size_t)h * DK_;
    const float* Kb = Ks + (size_t)b * L_ * HD_ + (size_t)h * DK_;
    const int lrow = tid >> 1, lcb = (tid & 1) * 32;

#pragma unroll
    for (int u = 0; u < 8; u++) {
        cp16(&Qt[lrow][lcb + u * 4], Qb + (size_t)(q0 + lrow) * HD_ + lcb + u * 4);
        cp16(&Kt[lrow][lcb + u * 4], Kb + (size_t)(n0 + lrow) * HD_ + lcb + u * 4);
    }
    cpcommit();

    float acc[2][8][4];
#pragma unroll
    for (int i = 0; i < 2; i++)
#pragma unroll
        for (int j = 0; j < 8; j++)
#pragma unroll
            for (int r = 0; r < 4; r++) acc[i][j][r] = 0.f;

    cpwait0();
    __syncthreads();

#pragma unroll
    for (int kk = 0; kk < 64; kk += 8) {
        unsigned af[2][4], bf[8][2];
#pragma unroll
        for (int i = 0; i < 2; i++) {
            const int mb = wr * 32 + i * 16;
            af[i][0] = Qt[mb + gm    ][kk + kq];
            af[i][1] = Qt[mb + gm + 8][kk + kq];
            af[i][2] = Qt[mb + gm    ][kk + kq + 4];
            af[i][3] = Qt[mb + gm + 8][kk + kq + 4];
        }
#pragma unroll
        for (int j = 0; j < 8; j++) {
            const int nb = wc * 64 + j * 8;
            bf[j][0] = Kt[nb + gm][kk + kq];
            bf[j][1] = Kt[nb + gm][kk + kq + 4];
        }
#pragma unroll
        for (int i = 0; i < 2; i++)
#pragma unroll
            for (int j = 0; j < 8; j++) mma8(acc[i][j], af[i], bf[j]);
    }

    float* outb = att + (size_t)(h * B_ + b) * L_ * L_;
    const unsigned char* mb = mask + (size_t)b * L_ * L_;

    // mask + scale in place, write raw S
#pragma unroll
    for (int i = 0; i < 2; i++)
#pragma unroll
        for (int j = 0; j < 8; j++) {
            const int q = q0 + wr * 32 + i * 16 + gm;
            const int k = n0 + wc * 64 + j * 8 + kq * 2;
            acc[i][j][0] = mb[(size_t)q * L_ + k]           ? -INFINITY : acc[i][j][0] * 0.125f;
            acc[i][j][1] = mb[(size_t)q * L_ + k + 1]       ? -INFINITY : acc[i][j][1] * 0.125f;
            acc[i][j][2] = mb[(size_t)(q + 8) * L_ + k]     ? -INFINITY : acc[i][j][2] * 0.125f;
            acc[i][j][3] = mb[(size_t)(q + 8) * L_ + k + 1] ? -INFINITY : acc[i][j][3] * 0.125f;
            *(float2*)(outb + (size_t)q * L_ + k)       = make_float2(acc[i][j][0], acc[i][j][1]);
            *(float2*)(outb + (size_t)(q + 8) * L_ + k) = make_float2(acc[i][j][2], acc[i][j][3]);
        }

    // per-thread row stats (2 rows per i), then quad reduce, then cross-warp
#pragma unroll
    for (int i = 0; i < 2; i++) {
        float m0 = -INFINITY, m1 = -INFINITY;
#pragma unroll
        for (int j = 0; j < 8; j++) {
            m0 = fmaxf(m0, fmaxf(acc[i][j][0], acc[i][j][1]));
            m1 = fmaxf(m1, fmaxf(acc[i][j][2], acc[i][j][3]));
        }
        float s0 = 0.f, s1 = 0.f;
#pragma unroll
        for (int j = 0; j < 8; j++) {
            s0 += __expf(acc[i][j][0] - m0) + __expf(acc[i][j][1] - m0);
            s1 += __expf(acc[i][j][2] - m1) + __expf(acc[i][j][3] - m1);
        }
#pragma unroll
        for (int off = 1; off <= 2; off <<= 1) {
            float mo = __shfl_xor_sync(0xffffffffu, m0, off);
            float so = __shfl_xor_sync(0xffffffffu, s0, off);
            float Mn = fmaxf(m0, mo);
            s0 = s0 * __expf(m0 - Mn) + so * __expf(mo - Mn); m0 = Mn;
            mo = __shfl_xor_sync(0xffffffffu, m1, off);
            so = __shfl_xor_sync(0xffffffffu, s1, off);
            Mn = fmaxf(m1, mo);
            s1 = s1 * __expf(m1 - Mn) + so * __expf(mo - Mn); m1 = Mn;
        }
        if (kq == 0) {
            const int r0 = wr * 32 + i * 16 + gm;
            pm[wc][r0] = m0; ps[wc][r0] = s0;
            pm[wc][r0 + 8] = m1; ps[wc][r0 + 8] = s1;
        }
    }
    __syncthreads();
    if (tid < 128) {
        float ma = pm[0][tid], sa = ps[0][tid];
        float mb2 = pm[1][tid], sb = ps[1][tid];
        float M = fmaxf(ma, mb2);
        float S = sa * __expf(ma - M) + sb * __expf(mb2 - M);
        part[((size_t)bh * 16 + blockIdx.x) * L_ + q0 + tid] = make_float2(M, S);
    }
}

// -------------- combine per-tile stats -> per-row (max, 1/sum) -------------------
__global__ __launch_bounds__(256) void rowstats(
    const float2* __restrict__ part, float2* __restrict__ rowMS)
{
    const int idx = blockIdx.x * 256 + threadIdx.x;   // bh*L + row
    const int bh = idx >> 11, row = idx & 2047;
    float M = -INFINITY, S = 0.f;
#pragma unroll
    for (int t = 0; t < 16; t++) {
        float2 p = part[((size_t)bh * 16 + t) * L_ + row];
        float Mn = fmaxf(M, p.x);
        S = S * __expf(M - Mn) + p.y * __expf(p.x - Mn);
        M = Mn;
    }
    rowMS[idx] = make_float2(M, 1.0f / S);
}

// ====== fused softmax-normalize + PV: p=exp(s-M)/S written to att; AO = p @ V =====
#define PSS 68
#define VSS 72
__global__ __launch_bounds__(256, 2) void pv_fused(
    float* __restrict__ att, const float* __restrict__ Vs,
    const float2* __restrict__ rowMS, float* __restrict__ AO)
{
    extern __shared__ unsigned sm[];
    unsigned (*Ps)[128][PSS] = (unsigned(*)[128][PSS])sm;
    unsigned (*Vt)[64][VSS]  = (unsigned(*)[64][VSS])(sm + 2 * 128 * PSS);

    const int tid  = threadIdx.x;
    const int lane = tid & 31, warp = tid >> 5;
    const int wr = warp >> 1, wc = warp & 1;
    const int gm = lane >> 2, kq = lane & 3;
    const int bh = blockIdx.y;
    const int b = bh >> 4, h = bh & 15;
    const int q0 = blockIdx.x * 128;

    float* Pb = att + (size_t)(h * B_ + b) * L_ * L_;
    const float* Vb = Vs + (size_t)b * L_ * HD_ + (size_t)h * DK_;

    // transform mapping: each thread owns one row, 32 cols
    const int prow = tid >> 1, pcb = (tid & 1) * 32;
    const float2 MS = rowMS[(size_t)bh * L_ + q0 + prow];
    // V load mapping
    const int vrow = tid >> 2, vcb = (tid & 3) * 16;

    float acc[2][4][4];
#pragma unroll
    for (int i = 0; i < 2; i++)
#pragma unroll
        for (int j = 0; j < 4; j++)
#pragma unroll
            for (int r = 0; r < 4; r++) acc[i][j][r] = 0.f;

    auto load = [&](int buf, int k0) {
#pragma unroll
        for (int u = 0; u < 8; u++)
            cp16(&Ps[buf][prow][pcb + u * 4],
                 Pb + (size_t)(q0 + prow) * L_ + k0 + pcb + u * 4);
#pragma unroll
        for (int u = 0; u < 4; u++)
            cp16(&Vt[buf][vrow][vcb + u * 4],
                 Vb + (size_t)(k0 + vrow) * HD_ + vcb + u * 4);
    };

    load(0, 0); cpcommit();
    int buf = 0;
    for (int k0 = 0; k0 < L_; k0 += 64) {
        cpwait0();
        __syncthreads();
        if (k0 + 64 < L_) { load(buf ^ 1, k0 + 64); cpcommit(); }

        // in-place softmax normalize; also write p to att
        float* prow_s = (float*)&Ps[buf][prow][pcb];
        float* prow_g = Pb + (size_t)(q0 + prow) * L_ + k0 + pcb;
#pragma unroll
        for (int u = 0; u < 8; u++) {
            float4 v = *(float4*)(prow_s + u * 4);
            v.x = __expf(v.x - MS.x) * MS.y;
            v.y = __expf(v.y - MS.x) * MS.y;
            v.z = __expf(v.z - MS.x) * MS.y;
            v.w = __expf(v.w - MS.x) * MS.y;
            *(float4*)(prow_s + u * 4) = v;
            *(float4*)(prow_g + u * 4) = v;
        }
        __syncthreads();

#pragma unroll
        for (int kk = 0; kk < 64; kk += 8) {
            unsigned af[2][4], bf[4][2];
#pragma unroll
            for (int i = 0; i < 2; i++) {
                const int mb = wr * 32 + i * 16;
                af[i][0] = Ps[buf][mb + gm    ][kk + kq];
                af[i][1] = Ps[buf][mb + gm + 8][kk + kq];
                af[i][2] = Ps[buf][mb + gm    ][kk + kq + 4];
                af[i][3] = Ps[buf][mb + gm + 8][kk + kq + 4];
            }
#pragma unroll
            for (int j = 0; j < 4; j++) {
                const int nb = wc * 32 + j * 8;
                bf[j][0] = Vt[buf][kk + kq    ][nb + gm];
                bf[j][1] = Vt[buf][kk + kq + 4][nb + gm];
            }
#pragma unroll
            for (int i = 0; i < 2; i++)
#pragma unroll
                for (int j = 0; j < 4; j++) mma8(acc[i][j], af[i], bf[j]);
        }
        buf ^= 1;
    }

#pragma unroll
    for (int i = 0; i < 2; i++)
#pragma unroll
        for (int j = 0; j < 4; j++) {
            const int q = q0 + wr * 32 + i * 16 + gm;
            const int col = wc * 32 + j * 8 + kq * 2;
            *(float2*)(AO + (size_t)(b * L_ + q) * HD_ + h * DK_ + col) =
                make_float2(acc[i][j][0], acc[i][j][1]);
            *(float2*)(AO + (size_t)(b * L_ + q + 8) * HD_ + h * DK_ + col) =
                make_float2(acc[i][j][2], acc[i][j][3]);
        }
}

// ---------------- residual + LayerNorm: y = LN(X + Q)*gamma + beta ---------------
__global__ __launch_bounds__(256) void ln_kernel(
    const float* __restrict__ X, const float* __restrict__ Qin,
    const float* __restrict__ gamma, const float* __restrict__ beta,
    float* __restrict__ y)
{
    __shared__ float red[8];
    const int row = blockIdx.x;
    const int tid = threadIdx.x;
    const float* xr = X + (size_t)row * DX_;
    const float* qr = Qin + (size_t)row * DX_;

    float x[4];
#pragma unroll
    for (int i = 0; i < 4; i++) x[i] = xr[tid + 256 * i] + qr[tid + 256 * i];

    float s = x[0] + x[1] + x[2] + x[3];
#pragma unroll
    for (int o = 16; o; o >>= 1) s += __shfl_xor_sync(0xffffffffu, s, o);
    if ((tid & 31) == 0) red[tid >> 5] = s;
    __syncthreads();
    s = red[0];
#pragma unroll
    for (int w = 1; w < 8; w++) s += red[w];
    const float mu = s * (1.0f / DX_);
    __syncthreads();

    float vs = 0.f;
#pragma unroll
    for (int i = 0; i < 4; i++) { float d = x[i] - mu; vs += d * d; }
#pragma unroll
    for (int o = 16; o; o >>= 1) vs += __shfl_xor_sync(0xffffffffu, vs, o);
    if ((tid & 31) == 0) red[tid >> 5] = vs;
    __syncthreads();
    vs = red[0];
#pragma unroll
    for (int w = 1; w < 8; w++) vs += red[w];
    const float var = vs * (1.0f / DX_);
    const float rs = rsqrtf(var + EPS_);

#pragma unroll
    for (int i = 0; i < 4; i++) {
        const int c = tid + 256 * i;
        y[(size_t)row * DX_ + c] = (x[i] - mu) * rs * gamma[c] + beta[c];
    }
}

// --------------------------------- launch ---------------------------------------
extern "C" void kernel_launch(void* const* d_in, const int* in_sizes, int n_in,
                              void* d_out, int out_size)
{
    const float* Q  = (const float*)d_in[0];
    const float* K  = (const float*)d_in[1];
    const float* V  = (const float*)d_in[2];
    const unsigned char* mask = (const unsigned char*)d_in[3];
    const float* Wq = (const float*)d_in[4];
    const float* bq = (const float*)d_in[5];
    const float* Wk = (const float*)d_in[6];
    const float* bk = (const float*)d_in[7];
    const float* Wv = (const float*)d_in[8];
    const float* bv = (const float*)d_in[9];
    const float* Wo = (const float*)d_in[10];
    const float* bo = (const float*)d_in[11];
    const float* gamma = (const float*)d_in[12];
    const float* beta  = (const float*)d_in[13];

    float* y   = (float*)d_out;
    float* att = (float*)d_out + (size_t)B_ * L_ * DX_;

    static float *pQs=nullptr,*pKs=nullptr,*pVs=nullptr,*pAO=nullptr,*pX=nullptr;
    static float2 *pPart=nullptr,*pRow=nullptr;
    if (!pQs) {
        cudaGetSymbolAddress((void**)&pQs, g_Qs);
        cudaGetSymbolAddress((void**)&pKs, g_Ks);
        cudaGetSymbolAddress((void**)&pVs, g_Vs);
        cudaGetSymbolAddress((void**)&pAO, g_AO);
        cudaGetSymbolAddress((void**)&pX,  g_X);
        cudaGetSymbolAddress((void**)&pPart, g_part);
        cudaGetSymbolAddress((void**)&pRow,  g_rowMS);
        cudaFuncSetAttribute(scores_tf32, cudaFuncAttributeMaxDynamicSharedMemorySize,
                             2 * 128 * SCS * 4);
        cudaFuncSetAttribute(pv_fused, cudaFuncAttributeMaxDynamicSharedMemorySize,
                             (2 * 128 * PSS + 2 * 64 * VSS) * 4);
    }

    const dim3 gProj(HD_ / 128, (B_ * L_) / 128);   // (8, 64)

    sgemm_tf32<<<gProj, 256>>>(Q, Wq, bq, pQs, B_ * L_, HD_, DX_);
    sgemm_tf32<<<gProj, 256>>>(K, Wk, bk, pKs, B_ * L_, HD_, DX_);
    sgemm_tf32<<<gProj, 256>>>(V, Wv, bv, pVs, B_ * L_, HD_, DX_);

    scores_tf32<<<dim3(L_ / 128, L_ / 128, B_ * H_), 256, 2 * 128 * SCS * 4>>>(
        pQs, pKs, mask, att, pPart);
    rowstats<<<(B_ * H_ * L_) / 256, 256>>>(pPart, pRow);
    pv_fused<<<dim3(L_ / 128, B_ * H_), 256, (2 * 128 * PSS + 2 * 64 * VSS) * 4>>>(
        att, pVs, pRow, pAO);

    sgemm_tf32<<<gProj, 256>>>(pAO, Wo, bo, pX, B_ * L_, DX_, HD_);
    ln_kernel<<<B_ * L_, 256>>>(pX, Q, gamma, beta, y);
}

// round 8
// speedup vs baseline: 1.0688x; 1.0688x over previous
#include <cuda_runtime.h>
#include <math.h>

#define B_   4
#define L_   2048
#define DX_  1024
#define H_   16
#define DK_  64
#define HD_  1024      // H*DK
#define EPS_ 1e-5f

// ---------------- scratch (device globals; no allocation allowed) ----------------
__device__ float g_Qs[(size_t)B_ * L_ * HD_];
__device__ float g_Ks[(size_t)B_ * L_ * HD_];
__device__ float g_Vs[(size_t)B_ * L_ * HD_];
__device__ float g_AO[(size_t)B_ * L_ * HD_];
__device__ float g_X [(size_t)B_ * L_ * DX_];
__device__ float g_rQ[(size_t)B_ * L_ * DX_];
__device__ float g_rK[(size_t)B_ * L_ * DX_];
__device__ float g_rV[(size_t)B_ * L_ * DX_];
__device__ float g_rWq[(size_t)DX_ * HD_];
__device__ float g_rWk[(size_t)DX_ * HD_];
__device__ float g_rWv[(size_t)DX_ * HD_];
__device__ float g_rWo[(size_t)HD_ * DX_];
__device__ float2 g_part [(size_t)B_ * H_ * 16 * L_];  // (b*16+h, k-tile, row): (max, expsum)
__device__ float2 g_rowMS[(size_t)B_ * H_ * L_];       // ATT-ORDER (h*B+b, row): (max, 1/sum)

// ---------------- tf32 / cp.async helpers ----------------------------------------
__device__ __forceinline__ unsigned f2tf(float x) {
    unsigned r; asm("cvt.rna.tf32.f32 %0, %1;" : "=r"(r) : "f"(x)); return r;
}
__device__ __forceinline__ float rndtf(float x) { return __uint_as_float(f2tf(x)); }

__device__ __forceinline__ void cp16(void* s, const void* g) {
    unsigned a = (unsigned)__cvta_generic_to_shared(s);
    asm volatile("cp.async.cg.shared.global [%0], [%1], 16;" :: "r"(a), "l"(g));
}
__device__ __forceinline__ void cpcommit() {
    asm volatile("cp.async.commit_group;" ::: "memory");
}
__device__ __forceinline__ void cpwait0() {
    asm volatile("cp.async.wait_group 0;" ::: "memory");
}

__device__ __forceinline__ void mma8(float* d, const unsigned* a, const unsigned* b) {
    asm volatile(
        "mma.sync.aligned.m16n8k8.row.col.f32.tf32.tf32.f32 "
        "{%0,%1,%2,%3},{%4,%5,%6,%7},{%8,%9},{%0,%1,%2,%3};"
        : "+f"(d[0]), "+f"(d[1]), "+f"(d[2]), "+f"(d[3])
        : "r"(a[0]), "r"(a[1]), "r"(a[2]), "r"(a[3]), "r"(b[0]), "r"(b[1]));
}

// ---------------- pre-round inputs to tf32 ---------------------------------------
__global__ __launch_bounds__(256) void round_tf32(
    const float4* __restrict__ in, float4* __restrict__ out, int n4)
{
    int i = blockIdx.x * blockDim.x + threadIdx.x;
    if (i < n4) {
        float4 v = in[i];
        v.x = rndtf(v.x); v.y = rndtf(v.y); v.z = rndtf(v.z); v.w = rndtf(v.w);
        out[i] = v;
    }
}

// ================= TF32 SGEMM: C[M,N] = A[M,K] @ B[K,N] + bias ===================
template<bool ROUND_OUT>
__global__ __launch_bounds__(256, 2) void sgemm_tf32(
    const float* __restrict__ A, const float* __restrict__ Bm,
    const float* __restrict__ bias, float* __restrict__ C,
    int M, int N, int K)
{
    __shared__ unsigned As[2][128][20];
    __shared__ unsigned Bs[2][16][136];
    const int tid  = threadIdx.x;
    const int lane = tid & 31, warp = tid >> 5;
    const int wr = warp >> 1, wc = warp & 1;
    const int gm = lane >> 2, kq = lane & 3;

    const float* Ab = A  + (size_t)(blockIdx.y * 128) * K;
    const float* Bb = Bm + blockIdx.x * 128;
    const int arow = tid >> 1,  acol = (tid & 1) * 8;
    const int brow = tid >> 4,  bcol = (tid & 15) * 8;

    float acc[2][8][4];
#pragma unroll
    for (int i = 0; i < 2; i++)
#pragma unroll
        for (int j = 0; j < 8; j++)
#pragma unroll
            for (int r = 0; r < 4; r++) acc[i][j][r] = 0.f;

    auto load = [&](int buf, int k0) {
        cp16(&As[buf][arow][acol],     Ab + (size_t)arow * K + k0 + acol);
        cp16(&As[buf][arow][acol + 4], Ab + (size_t)arow * K + k0 + acol + 4);
        cp16(&Bs[buf][brow][bcol],     Bb + (size_t)(k0 + brow) * N + bcol);
        cp16(&Bs[buf][brow][bcol + 4], Bb + (size_t)(k0 + brow) * N + bcol + 4);
    };

    load(0, 0); cpcommit();
    int buf = 0;
    for (int k0 = 0; k0 < K; k0 += 16) {
        cpwait0();
        __syncthreads();
        if (k0 + 16 < K) { load(buf ^ 1, k0 + 16); cpcommit(); }
#pragma unroll
        for (int kk = 0; kk < 16; kk += 8) {
            unsigned af[2][4], bf[8][2];
#pragma unroll
            for (int i = 0; i < 2; i++) {
                const int mb = wr * 32 + i * 16;
                af[i][0] = As[buf][mb + gm    ][kk + kq];
                af[i][1] = As[buf][mb + gm + 8][kk + kq];
                af[i][2] = As[buf][mb + gm    ][kk + kq + 4];
                af[i][3] = As[buf][mb + gm + 8][kk + kq + 4];
            }
#pragma unroll
            for (int j = 0; j < 8; j++) {
                const int nb = wc * 64 + j * 8;
                bf[j][0] = Bs[buf][kk + kq    ][nb + gm];
                bf[j][1] = Bs[buf][kk + kq + 4][nb + gm];
            }
#pragma unroll
            for (int i = 0; i < 2; i++)
#pragma unroll
                for (int j = 0; j < 8; j++) mma8(acc[i][j], af[i], bf[j]);
        }
        __syncthreads();
        buf ^= 1;
    }

#pragma unroll
    for (int i = 0; i < 2; i++)
#pragma unroll
        for (int j = 0; j < 8; j++) {
            const int row = blockIdx.y * 128 + wr * 32 + i * 16 + gm;
            const int col = blockIdx.x * 128 + wc * 64 + j * 8 + kq * 2;
            float2 bv = *(const float2*)(bias + col);
            float2 o0, o1;
            o0.x = acc[i][j][0] + bv.x; o0.y = acc[i][j][1] + bv.y;
            o1.x = acc[i][j][2] + bv.x; o1.y = acc[i][j][3] + bv.y;
            if (ROUND_OUT) {
                o0.x = rndtf(o0.x); o0.y = rndtf(o0.y);
                o1.x = rndtf(o1.x); o1.y = rndtf(o1.y);
            }
            *(float2*)(C + (size_t)row * N + col)       = o0;
            *(float2*)(C + (size_t)(row + 8) * N + col) = o1;
        }
}

// ============ scores: S = (Qh @ Kh^T)/8 masked; raw S + per-tile row stats ========
#define SCS 68
__global__ __launch_bounds__(256, 2) void scores_tf32(
    const float* __restrict__ Qs, const float* __restrict__ Ks,
    const unsigned char* __restrict__ mask, float* __restrict__ att,
    float2* __restrict__ part)
{
    extern __shared__ unsigned sm[];
    unsigned (*Qt)[SCS] = (unsigned(*)[SCS])sm;
    unsigned (*Kt)[SCS] = (unsigned(*)[SCS])(sm + 128 * SCS);
    unsigned char* msk = (unsigned char*)sm;     // reused after mainloop: 128x128 bytes
    __shared__ float pm[2][128], ps[2][128];

    const int tid  = threadIdx.x;
    const int lane = tid & 31, warp = tid >> 5;
    const int wr = warp >> 1, wc = warp & 1;
    const int gm = lane >> 2, kq = lane & 3;
    const int bh = blockIdx.z;                  // b*16 + h
    const int b = bh >> 4, h = bh & 15;
    const int q0 = blockIdx.y * 128, n0 = blockIdx.x * 128;

    const float* Qb = Qs + (size_t)b * L_ * HD_ + (size_t)h * DK_;
    const float* Kb = Ks + (size_t)b * L_ * HD_ + (size_t)h * DK_;
    const int lrow = tid >> 1, lcb = (tid & 1) * 32;

#pragma unroll
    for (int u = 0; u < 8; u++) {
        cp16(&Qt[lrow][lcb + u * 4], Qb + (size_t)(q0 + lrow) * HD_ + lcb + u * 4);
        cp16(&Kt[lrow][lcb + u * 4], Kb + (size_t)(n0 + lrow) * HD_ + lcb + u * 4);
    }
    cpcommit();

    float acc[2][8][4];
#pragma unroll
    for (int i = 0; i < 2; i++)
#pragma unroll
        for (int j = 0; j < 8; j++)
#pragma unroll
            for (int r = 0; r < 4; r++) acc[i][j][r] = 0.f;

    cpwait0();
    __syncthreads();

#pragma unroll
    for (int kk = 0; kk < 64; kk += 8) {
        unsigned af[2][4], bf[8][2];
#pragma unroll
        for (int i = 0; i < 2; i++) {
            const int mb = wr * 32 + i * 16;
            af[i][0] = Qt[mb + gm    ][kk + kq];
            af[i][1] = Qt[mb + gm + 8][kk + kq];
            af[i][2] = Qt[mb + gm    ][kk + kq + 4];
            af[i][3] = Qt[mb + gm + 8][kk + kq + 4];
        }
#pragma unroll
        for (int j = 0; j < 8; j++) {
            const int nb = wc * 64 + j * 8;
            bf[j][0] = Kt[nb + gm][kk + kq];
            bf[j][1] = Kt[nb + gm][kk + kq + 4];
        }
#pragma unroll
        for (int i = 0; i < 2; i++)
#pragma unroll
            for (int j = 0; j < 8; j++) mma8(acc[i][j], af[i], bf[j]);
    }

    // ---- stage mask tile into smem (Qt/Kt dead now) with coalesced 16B loads ----
    __syncthreads();
    {
        const unsigned char* mg = mask + (size_t)b * L_ * L_
                                 + (size_t)(q0 + (tid >> 1)) * L_ + n0 + (tid & 1) * 64;
        unsigned char* msrow = msk + (tid >> 1) * 128 + (tid & 1) * 64;
#pragma unroll
        for (int u = 0; u < 4; u++)
            cp16(msrow + u * 16, mg + u * 16);
    }
    cpcommit(); cpwait0();
    __syncthreads();

    float* outb = att + (size_t)(h * B_ + b) * L_ * L_;

    // mask + scale in place (from smem), write raw S
#pragma unroll
    for (int i = 0; i < 2; i++)
#pragma unroll
        for (int j = 0; j < 8; j++) {
            const int ql = wr * 32 + i * 16 + gm;
            const int kl = wc * 64 + j * 8 + kq * 2;
            acc[i][j][0] = msk[ql * 128 + kl]           ? -INFINITY : acc[i][j][0] * 0.125f;
            acc[i][j][1] = msk[ql * 128 + kl + 1]       ? -INFINITY : acc[i][j][1] * 0.125f;
            acc[i][j][2] = msk[(ql + 8) * 128 + kl]     ? -INFINITY : acc[i][j][2] * 0.125f;
            acc[i][j][3] = msk[(ql + 8) * 128 + kl + 1] ? -INFINITY : acc[i][j][3] * 0.125f;
            *(float2*)(outb + (size_t)(q0 + ql) * L_ + n0 + kl) =
                make_float2(acc[i][j][0], acc[i][j][1]);
            *(float2*)(outb + (size_t)(q0 + ql + 8) * L_ + n0 + kl) =
                make_float2(acc[i][j][2], acc[i][j][3]);
        }

    // per-thread row stats (2 rows per i), quad reduce, cross-warp-col combine
#pragma unroll
    for (int i = 0; i < 2; i++) {
        float m0 = -INFINITY, m1 = -INFINITY;
#pragma unroll
        for (int j = 0; j < 8; j++) {
            m0 = fmaxf(m0, fmaxf(acc[i][j][0], acc[i][j][1]));
            m1 = fmaxf(m1, fmaxf(acc[i][j][2], acc[i][j][3]));
        }
        float s0 = 0.f, s1 = 0.f;
#pragma unroll
        for (int j = 0; j < 8; j++) {
            s0 += __expf(acc[i][j][0] - m0) + __expf(acc[i][j][1] - m0);
            s1 += __expf(acc[i][j][2] - m1) + __expf(acc[i][j][3] - m1);
        }
#pragma unroll
        for (int off = 1; off <= 2; off <<= 1) {
            float mo = __shfl_xor_sync(0xffffffffu, m0, off);
            float so = __shfl_xor_sync(0xffffffffu, s0, off);
            float Mn = fmaxf(m0, mo);
            s0 = s0 * __expf(m0 - Mn) + so * __expf(mo - Mn); m0 = Mn;
            mo = __shfl_xor_sync(0xffffffffu, m1, off);
            so = __shfl_xor_sync(0xffffffffu, s1, off);
            Mn = fmaxf(m1, mo);
            s1 = s1 * __expf(m1 - Mn) + so * __expf(mo - Mn); m1 = Mn;
        }
        if (kq == 0) {
            const int r0 = wr * 32 + i * 16 + gm;
            pm[wc][r0] = m0; ps[wc][r0] = s0;
            pm[wc][r0 + 8] = m1; ps[wc][r0 + 8] = s1;
        }
    }
    __syncthreads();
    if (tid < 128) {
        float ma = pm[0][tid], sa = ps[0][tid];
        float mb2 = pm[1][tid], sb = ps[1][tid];
        float M = fmaxf(ma, mb2);
        float S = sa * __expf(ma - M) + sb * __expf(mb2 - M);
        part[((size_t)bh * 16 + blockIdx.x) * L_ + q0 + tid] = make_float2(M, S);
    }
}

// ------ combine per-tile stats -> per-row (max, 1/sum), REORDERED to att layout ---
// part is indexed by bh = b*16+h; output rowMS is indexed by hb = h*B+b (att order).
__global__ __launch_bounds__(256) void rowstats(
    const float2* __restrict__ part, float2* __restrict__ rowMS)
{
    const int idx = blockIdx.x * 256 + threadIdx.x;   // bh*L + row, bh = b*16+h
    const int bh = idx >> 11, row = idx & 2047;
    const int b = bh >> 4, h = bh & 15;
    float M = -INFINITY, S = 0.f;
#pragma unroll
    for (int t = 0; t < 16; t++) {
        float2 p = part[((size_t)bh * 16 + t) * L_ + row];
        float Mn = fmaxf(M, p.x);
        S = S * __expf(M - Mn) + p.y * __expf(p.x - Mn);
        M = Mn;
    }
    rowMS[(size_t)(h * B_ + b) * L_ + row] = make_float2(M, 1.0f / S);
}

// -------- streaming normalize: p = rndtf(exp(s - M) * invS), in place ------------
// blockIdx.x enumerates att rows linearly (att order = h*B+b); rowMS same order.
__global__ __launch_bounds__(256) void normalize_kernel(
    float* __restrict__ att, const float2* __restrict__ rowMS)
{
    const float2 MS = rowMS[blockIdx.x];
    float4* row = (float4*)(att + (size_t)blockIdx.x * L_);
    const int tid = threadIdx.x;
#pragma unroll
    for (int u = 0; u < 2; u++) {
        float4 v = row[u * 256 + tid];
        v.x = rndtf(__expf(v.x - MS.x) * MS.y);
        v.y = rndtf(__expf(v.y - MS.x) * MS.y);
        v.z = rndtf(__expf(v.z - MS.x) * MS.y);
        v.w = rndtf(__expf(v.w - MS.x) * MS.y);
        row[u * 256 + tid] = v;
    }
}

// ============ PV: AO[b,q,h,:] = P[b,h,q,:] @ Vh[2048,64] ========================
#define PTS 36
#define VTS 72
__global__ __launch_bounds__(256, 2) void pv_tf32(
    const float* __restrict__ att, const float* __restrict__ Vs,
    float* __restrict__ AO)
{
    extern __shared__ unsigned sm[];
    unsigned (*Pt)[128][PTS] = (unsigned(*)[128][PTS])sm;
    unsigned (*Vt)[32][VTS]  = (unsigned(*)[32][VTS])(sm + 2 * 128 * PTS);

    const int tid  = threadIdx.x;
    const int lane = tid & 31, warp = tid >> 5;
    const int wr = warp >> 1, wc = warp & 1;
    const int gm = lane >> 2, kq = lane & 3;
    const int bh = blockIdx.y;
    const int b = bh >> 4, h = bh & 15;
    const int q0 = blockIdx.x * 128;

    const float* Pb = att + (size_t)(h * B_ + b) * L_ * L_;
    const float* Vb = Vs + (size_t)b * L_ * HD_ + (size_t)h * DK_;
    const int prow = tid >> 1, pcb = (tid & 1) * 16;
    const int vrow = tid >> 3, vcb = (tid & 7) * 8;

    float acc[2][4][4];
#pragma unroll
    for (int i = 0; i < 2; i++)
#pragma unroll
        for (int j = 0; j < 4; j++)
#pragma unroll
            for (int r = 0; r < 4; r++) acc[i][j][r] = 0.f;

    auto load = [&](int buf, int k0) {
#pragma unroll
        for (int u = 0; u < 4; u++)
            cp16(&Pt[buf][prow][pcb + u * 4],
                 Pb + (size_t)(q0 + prow) * L_ + k0 + pcb + u * 4);
#pragma unroll
        for (int u = 0; u < 2; u++)
            cp16(&Vt[buf][vrow][vcb + u * 4],
                 Vb + (size_t)(k0 + vrow) * HD_ + vcb + u * 4);
    };

    load(0, 0); cpcommit();
    int buf = 0;
    for (int k0 = 0; k0 < L_; k0 += 32) {
        cpwait0();
        __syncthreads();
        if (k0 + 32 < L_) { load(buf ^ 1, k0 + 32); cpcommit(); }
#pragma unroll
        for (int kk = 0; kk < 32; kk += 8) {
            unsigned af[2][4], bf[4][2];
#pragma unroll
            for (int i = 0; i < 2; i++) {
                const int mb = wr * 32 + i * 16;
                af[i][0] = Pt[buf][mb + gm    ][kk + kq];
                af[i][1] = Pt[buf][mb + gm + 8][kk + kq];
                af[i][2] = Pt[buf][mb + gm    ][kk + kq + 4];
                af[i][3] = Pt[buf][mb + gm + 8][kk + kq + 4];
            }
#pragma unroll
            for (int j = 0; j < 4; j++) {
                const int nb = wc * 32 + j * 8;
                bf[j][0] = Vt[buf][kk + kq    ][nb + gm];
                bf[j][1] = Vt[buf][kk + kq + 4][nb + gm];
            }
#pragma unroll
            for (int i = 0; i < 2; i++)
#pragma unroll
                for (int j = 0; j < 4; j++) mma8(acc[i][j], af[i], bf[j]);
        }
        __syncthreads();
        buf ^= 1;
    }

#pragma unroll
    for (int i = 0; i < 2; i++)
#pragma unroll
        for (int j = 0; j < 4; j++) {
            const int q = q0 + wr * 32 + i * 16 + gm;
            const int col = wc * 32 + j * 8 + kq * 2;
            float2 o0, o1;
            o0.x = rndtf(acc[i][j][0]); o0.y = rndtf(acc[i][j][1]);
            o1.x = rndtf(acc[i][j][2]); o1.y = rndtf(acc[i][j][3]);
            *(float2*)(AO + (size_t)(b * L_ + q) * HD_ + h * DK_ + col)      = o0;
            *(float2*)(AO + (size_t)(b * L_ + q + 8) * HD_ + h * DK_ + col) = o1;
        }
}

// ---------------- residual + LayerNorm: y = LN(X + Q)*gamma + beta ---------------
__global__ __launch_bounds__(256) void ln_kernel(
    const float* __restrict__ X, const float* __restrict__ Qin,
    const float* __restrict__ gamma, const float* __restrict__ beta,
    float* __restrict__ y)
{
    __shared__ float red[8];
    const int row = blockIdx.x;
    const int tid = threadIdx.x;
    const float* xr = X + (size_t)row * DX_;
    const float* qr = Qin + (size_t)row * DX_;

    float x[4];
#pragma unroll
    for (int i = 0; i < 4; i++) x[i] = xr[tid + 256 * i] + qr[tid + 256 * i];

    float s = x[0] + x[1] + x[2] + x[3];
#pragma unroll
    for (int o = 16; o; o >>= 1) s += __shfl_xor_sync(0xffffffffu, s, o);
    if ((tid & 31) == 0) red[tid >> 5] = s;
    __syncthreads();
    s = red[0];
#pragma unroll
    for (int w = 1; w < 8; w++) s += red[w];
    const float mu = s * (1.0f / DX_);
    __syncthreads();

    float vs = 0.f;
#pragma unroll
    for (int i = 0; i < 4; i++) { float d = x[i] - mu; vs += d * d; }
#pragma unroll
    for (int o = 16; o; o >>= 1) vs += __shfl_xor_sync(0xffffffffu, vs, o);
    if ((tid & 31) == 0) red[tid >> 5] = vs;
    __syncthreads();
    vs = red[0];
#pragma unroll
    for (int w = 1; w < 8; w++) vs += red[w];
    const float var = vs * (1.0f / DX_);
    const float rs = rsqrtf(var + EPS_);

#pragma unroll
    for (int i = 0; i < 4; i++) {
        const int c = tid + 256 * i;
        y[(size_t)row * DX_ + c] = (x[i] - mu) * rs * gamma[c] + beta[c];
    }
}

// --------------------------------- launch ---------------------------------------
extern "C" void kernel_launch(void* const* d_in, const int* in_sizes, int n_in,
                              void* d_out, int out_size)
{
    const float* Q  = (const float*)d_in[0];
    const float* K  = (const float*)d_in[1];
    const float* V  = (const float*)d_in[2];
    const unsigned char* mask = (const unsigned char*)d_in[3];
    const float* Wq = (const float*)d_in[4];
    const float* bq = (const float*)d_in[5];
    const float* Wk = (const float*)d_in[6];
    const float* bk = (const float*)d_in[7];
    const float* Wv = (const float*)d_in[8];
    const float* bv = (const float*)d_in[9];
    const float* Wo = (const float*)d_in[10];
    const float* bo = (const float*)d_in[11];
    const float* gamma = (const float*)d_in[12];
    const float* beta  = (const float*)d_in[13];

    float* y   = (float*)d_out;
    float* att = (float*)d_out + (size_t)B_ * L_ * DX_;

    static float *pQs=nullptr,*pKs=nullptr,*pVs=nullptr,*pAO=nullptr,*pX=nullptr;
    static float *prQ=nullptr,*prK=nullptr,*prV=nullptr;
    static float *prWq=nullptr,*prWk=nullptr,*prWv=nullptr,*prWo=nullptr;
    static float2 *pPart=nullptr,*pRow=nullptr;
    if (!pQs) {
        cudaGetSymbolAddress((void**)&pQs, g_Qs);
        cudaGetSymbolAddress((void**)&pKs, g_Ks);
        cudaGetSymbolAddress((void**)&pVs, g_Vs);
        cudaGetSymbolAddress((void**)&pAO, g_AO);
        cudaGetSymbolAddress((void**)&pX,  g_X);
        cudaGetSymbolAddress((void**)&prQ, g_rQ);
        cudaGetSymbolAddress((void**)&prK, g_rK);
        cudaGetSymbolAddress((void**)&prV, g_rV);
        cudaGetSymbolAddress((void**)&prWq, g_rWq);
        cudaGetSymbolAddress((void**)&prWk, g_rWk);
        cudaGetSymbolAddress((void**)&prWv, g_rWv);
        cudaGetSymbolAddress((void**)&prWo, g_rWo);
        cudaGetSymbolAddress((void**)&pPart, g_part);
        cudaGetSymbolAddress((void**)&pRow,  g_rowMS);
        cudaFuncSetAttribute(scores_tf32, cudaFuncAttributeMaxDynamicSharedMemorySize,
                             2 * 128 * SCS * 4);
        cudaFuncSetAttribute(pv_tf32, cudaFuncAttributeMaxDynamicSharedMemorySize,
                             (2 * 128 * PTS + 2 * 32 * VTS) * 4);
    }

    const int nBig = B_ * L_ * DX_ / 4;
    const int nW   = DX_ * HD_ / 4;
    round_tf32<<<nBig / 256, 256>>>((const float4*)Q, (float4*)prQ, nBig);
    round_tf32<<<nBig / 256, 256>>>((const float4*)K, (float4*)prK, nBig);
    round_tf32<<<nBig / 256, 256>>>((const float4*)V, (float4*)prV, nBig);
    round_tf32<<<nW / 256, 256>>>((const float4*)Wq, (float4*)prWq, nW);
    round_tf32<<<nW / 256, 256>>>((const float4*)Wk, (float4*)prWk, nW);
    round_tf32<<<nW / 256, 256>>>((const float4*)Wv, (float4*)prWv, nW);
    round_tf32<<<nW / 256, 256>>>((const float4*)Wo, (float4*)prWo, nW);

    const dim3 gProj(HD_ / 128, (B_ * L_) / 128);   // (8, 64)

    sgemm_tf32<true><<<gProj, 256>>>(prQ, prWq, bq, pQs, B_ * L_, HD_, DX_);
    sgemm_tf32<true><<<gProj, 256>>>(prK, prWk, bk, pKs, B_ * L_, HD_, DX_);
    sgemm_tf32<true><<<gProj, 256>>>(prV, prWv, bv, pVs, B_ * L_, HD_, DX_);

    scores_tf32<<<dim3(L_ / 128, L_ / 128, B_ * H_), 256, 2 * 128 * SCS * 4>>>(
        pQs, pKs, mask, att, pPart);
    rowstats<<<(B_ * H_ * L_) / 256, 256>>>(pPart, pRow);
    normalize_kernel<<<B_ * H_ * L_, 256>>>(att, pRow);
    pv_tf32<<<dim3(L_ / 128, B_ * H_), 256, (2 * 128 * PTS + 2 * 32 * VTS) * 4>>>(
        att, pVs, pAO);

    sgemm_tf32<false><<<gProj, 256>>>(pAO, prWo, bo, pX, B_ * L_, DX_, HD_);
    ln_kernel<<<B_ * L_, 256>>>(pX, Q, gamma, beta, y);
}

// round 10
// speedup vs baseline: 1.1235x; 1.0512x over previous
#include <cuda_runtime.h>
#include <math.h>
#include <stdint.h>

#define B_   4
#define L_   2048
#define DX_  1024
#define H_   16
#define DK_  64
#define HD_  1024      // H*DK
#define EPS_ 1e-5f

// ---------------- scratch (device globals; no allocation allowed) ----------------
__device__ float g_Qs[(size_t)B_ * L_ * HD_];
__device__ float g_Ks[(size_t)B_ * L_ * HD_];
__device__ float g_Vs[(size_t)B_ * L_ * HD_];
__device__ float g_AO[(size_t)B_ * L_ * HD_];
__device__ float g_X [(size_t)B_ * L_ * DX_];
__device__ float g_rWq[(size_t)DX_ * HD_];   // tf32-rounded weights, [K][N] layout
__device__ float g_rWk[(size_t)DX_ * HD_];
__device__ float g_rWv[(size_t)DX_ * HD_];
__device__ float g_rWo[(size_t)HD_ * DX_];
__device__ float2 g_part[(size_t)B_ * H_ * 16 * L_];  // (b*16+h, k-tile, row): (max, expsum)

// ---------------- tf32 / cp.async helpers ----------------------------------------
__device__ __forceinline__ unsigned f2tf(float x) {
    unsigned r; asm("cvt.rna.tf32.f32 %0, %1;" : "=r"(r) : "f"(x)); return r;
}
__device__ __forceinline__ float rndtf(float x) { return __uint_as_float(f2tf(x)); }

__device__ __forceinline__ void cp16(void* s, const void* g) {
    unsigned a = (unsigned)__cvta_generic_to_shared(s);
    asm volatile("cp.async.cg.shared.global [%0], [%1], 16;" :: "r"(a), "l"(g));
}
__device__ __forceinline__ void cpcommit() {
    asm volatile("cp.async.commit_group;" ::: "memory");
}
__device__ __forceinline__ void cpwait0() {
    asm volatile("cp.async.wait_group 0;" ::: "memory");
}

__device__ __forceinline__ void mma8(float* d, const unsigned* a, const unsigned* b) {
    asm volatile(
        "mma.sync.aligned.m16n8k8.row.col.f32.tf32.tf32.f32 "
        "{%0,%1,%2,%3},{%4,%5,%6,%7},{%8,%9},{%0,%1,%2,%3};"
        : "+f"(d[0]), "+f"(d[1]), "+f"(d[2]), "+f"(d[3])
        : "r"(a[0]), "r"(a[1]), "r"(a[2]), "r"(a[3]), "r"(b[0]), "r"(b[1]));
}

// ---------------- pre-round weights to tf32 (weights only now) --------------------
__global__ __launch_bounds__(256) void round_tf32(
    const float4* __restrict__ in, float4* __restrict__ out, int n4)
{
    int i = blockIdx.x * blockDim.x + threadIdx.x;
    if (i < n4) {
        float4 v = in[i];
        v.x = rndtf(v.x); v.y = rndtf(v.y); v.z = rndtf(v.z); v.w = rndtf(v.w);
        out[i] = v;
    }
}

// ================= TF32 SGEMM: C[M,N] = A[M,K] @ B[K,N] + bias ===================
// A is RAW fp32 (rounded to tf32 in-register at fragment load); B is pre-rounded.
template<bool ROUND_OUT>
__global__ __launch_bounds__(256, 2) void sgemm_tf32(
    const float* __restrict__ A, const float* __restrict__ Bm,
    const float* __restrict__ bias, float* __restrict__ C,
    int M, int N, int K)
{
    __shared__ unsigned As[2][128][20];
    __shared__ unsigned Bs[2][16][136];
    const int tid  = threadIdx.x;
    const int lane = tid & 31, warp = tid >> 5;
    const int wr = warp >> 1, wc = warp & 1;
    const int gm = lane >> 2, kq = lane & 3;

    const float* Ab = A  + (size_t)(blockIdx.y * 128) * K;
    const float* Bb = Bm + blockIdx.x * 128;
    const int arow = tid >> 1,  acol = (tid & 1) * 8;
    const int brow = tid >> 4,  bcol = (tid & 15) * 8;

    float acc[2][8][4];
#pragma unroll
    for (int i = 0; i < 2; i++)
#pragma unroll
        for (int j = 0; j < 8; j++)
#pragma unroll
            for (int r = 0; r < 4; r++) acc[i][j][r] = 0.f;

    auto load = [&](int buf, int k0) {
        cp16(&As[buf][arow][acol],     Ab + (size_t)arow * K + k0 + acol);
        cp16(&As[buf][arow][acol + 4], Ab + (size_t)arow * K + k0 + acol + 4);
        cp16(&Bs[buf][brow][bcol],     Bb + (size_t)(k0 + brow) * N + bcol);
        cp16(&Bs[buf][brow][bcol + 4], Bb + (size_t)(k0 + brow) * N + bcol + 4);
    };

    load(0, 0); cpcommit();
    int buf = 0;
    for (int k0 = 0; k0 < K; k0 += 16) {
        cpwait0();
        __syncthreads();
        if (k0 + 16 < K) { load(buf ^ 1, k0 + 16); cpcommit(); }
#pragma unroll
        for (int kk = 0; kk < 16; kk += 8) {
            unsigned af[2][4], bf[8][2];
#pragma unroll
            for (int i = 0; i < 2; i++) {
                const int mb = wr * 32 + i * 16;
                // A raw fp32 -> tf32 RNA in-register (bit-identical to pre-rounding)
                af[i][0] = f2tf(__uint_as_float(As[buf][mb + gm    ][kk + kq]));
                af[i][1] = f2tf(__uint_as_float(As[buf][mb + gm + 8][kk + kq]));
                af[i][2] = f2tf(__uint_as_float(As[buf][mb + gm    ][kk + kq + 4]));
                af[i][3] = f2tf(__uint_as_float(As[buf][mb + gm + 8][kk + kq + 4]));
            }
#pragma unroll
            for (int j = 0; j < 8; j++) {
                const int nb = wc * 64 + j * 8;
                bf[j][0] = Bs[buf][kk + kq    ][nb + gm];
                bf[j][1] = Bs[buf][kk + kq + 4][nb + gm];
            }
#pragma unroll
            for (int i = 0; i < 2; i++)
#pragma unroll
                for (int j = 0; j < 8; j++) mma8(acc[i][j], af[i], bf[j]);
        }
        __syncthreads();
        buf ^= 1;
    }

#pragma unroll
    for (int i = 0; i < 2; i++)
#pragma unroll
        for (int j = 0; j < 8; j++) {
            const int row = blockIdx.y * 128 + wr * 32 + i * 16 + gm;
            const int col = blockIdx.x * 128 + wc * 64 + j * 8 + kq * 2;
            float2 bv = *(const float2*)(bias + col);
            float2 o0, o1;
            o0.x = acc[i][j][0] + bv.x; o0.y = acc[i][j][1] + bv.y;
            o1.x = acc[i][j][2] + bv.x; o1.y = acc[i][j][3] + bv.y;
            if (ROUND_OUT) {
                o0.x = rndtf(o0.x); o0.y = rndtf(o0.y);
                o1.x = rndtf(o1.x); o1.y = rndtf(o1.y);
            }
            *(float2*)(C + (size_t)row * N + col)       = o0;
            *(float2*)(C + (size_t)(row + 8) * N + col) = o1;
        }
}

// ============ scores: S = (Qh @ Kh^T)/8 masked; raw S + per-tile row stats ========
#define SCS 68
__global__ __launch_bounds__(256, 2) void scores_tf32(
    const float* __restrict__ Qs, const float* __restrict__ Ks,
    const unsigned char* __restrict__ mask, float* __restrict__ att,
    float2* __restrict__ part)
{
    extern __shared__ unsigned sm[];
    unsigned (*Qt)[SCS] = (unsigned(*)[SCS])sm;
    unsigned (*Kt)[SCS] = (unsigned(*)[SCS])(sm + 128 * SCS);
    unsigned char* msk = (unsigned char*)sm;     // reused after mainloop
    __shared__ float pm[2][128], ps[2][128];

    const int tid  = threadIdx.x;
    const int lane = tid & 31, warp = tid >> 5;
    const int wr = warp >> 1, wc = warp & 1;
    const int gm = lane >> 2, kq = lane & 3;
    const int bh = blockIdx.z;                  // b*16 + h
    const int b = bh >> 4, h = bh & 15;
    const int q0 = blockIdx.y * 128, n0 = blockIdx.x * 128;

    const float* Qb = Qs + (size_t)b * L_ * HD_ + (size_t)h * DK_;
    const float* Kb = Ks + (size_t)b * L_ * HD_ + (size_t)h * DK_;
    const int lrow = tid >> 1, lcb = (tid & 1) * 32;

#pragma unroll
    for (int u = 0; u < 8; u++) {
        cp16(&Qt[lrow][lcb + u * 4], Qb + (size_t)(q0 + lrow) * HD_ + lcb + u * 4);
        cp16(&Kt[lrow][lcb + u * 4], Kb + (size_t)(n0 + lrow) * HD_ + lcb + u * 4);
    }
    cpcommit();

    float acc[2][8][4];
#pragma unroll
    for (int i = 0; i < 2; i++)
#pragma unroll
        for (int j = 0; j < 8; j++)
#pragma unroll
            for (int r = 0; r < 4; r++) acc[i][j][r] = 0.f;

    cpwait0();
    __syncthreads();

#pragma unroll
    for (int kk = 0; kk < 64; kk += 8) {
        unsigned af[2][4], bf[8][2];
#pragma unroll
        for (int i = 0; i < 2; i++) {
            const int mb = wr * 32 + i * 16;
            af[i][0] = Qt[mb + gm    ][kk + kq];
            af[i][1] = Qt[mb + gm + 8][kk + kq];
            af[i][2] = Qt[mb + gm    ][kk + kq + 4];
            af[i][3] = Qt[mb + gm + 8][kk + kq + 4];
        }
#pragma unroll
        for (int j = 0; j < 8; j++) {
            const int nb = wc * 64 + j * 8;
            bf[j][0] = Kt[nb + gm][kk + kq];
            bf[j][1] = Kt[nb + gm][kk + kq + 4];
        }
#pragma unroll
        for (int i = 0; i < 2; i++)
#pragma unroll
            for (int j = 0; j < 8; j++) mma8(acc[i][j], af[i], bf[j]);
    }

    __syncthreads();
    {
        const unsigned char* mg = mask + (size_t)b * L_ * L_
                                 + (size_t)(q0 + (tid >> 1)) * L_ + n0 + (tid & 1) * 64;
        unsigned char* msrow = msk + (tid >> 1) * 128 + (tid & 1) * 64;
#pragma unroll
        for (int u = 0; u < 4; u++)
            cp16(msrow + u * 16, mg + u * 16);
    }
    cpcommit(); cpwait0();
    __syncthreads();

    float* outb = att + (size_t)(h * B_ + b) * L_ * L_;

#pragma unroll
    for (int i = 0; i < 2; i++)
#pragma unroll
        for (int j = 0; j < 8; j++) {
            const int ql = wr * 32 + i * 16 + gm;
            const int kl = wc * 64 + j * 8 + kq * 2;
            acc[i][j][0] = msk[ql * 128 + kl]           ? -INFINITY : acc[i][j][0] * 0.125f;
            acc[i][j][1] = msk[ql * 128 + kl + 1]       ? -INFINITY : acc[i][j][1] * 0.125f;
            acc[i][j][2] = msk[(ql + 8) * 128 + kl]     ? -INFINITY : acc[i][j][2] * 0.125f;
            acc[i][j][3] = msk[(ql + 8) * 128 + kl + 1] ? -INFINITY : acc[i][j][3] * 0.125f;
            *(float2*)(outb + (size_t)(q0 + ql) * L_ + n0 + kl) =
                make_float2(acc[i][j][0], acc[i][j][1]);
            *(float2*)(outb + (size_t)(q0 + ql + 8) * L_ + n0 + kl) =
                make_float2(acc[i][j][2], acc[i][j][3]);
        }

#pragma unroll
    for (int i = 0; i < 2; i++) {
        float m0 = -INFINITY, m1 = -INFINITY;
#pragma unroll
        for (int j = 0; j < 8; j++) {
            m0 = fmaxf(m0, fmaxf(acc[i][j][0], acc[i][j][1]));
            m1 = fmaxf(m1, fmaxf(acc[i][j][2], acc[i][j][3]));
        }
        float s0 = 0.f, s1 = 0.f;
#pragma unroll
        for (int j = 0; j < 8; j++) {
            s0 += __expf(acc[i][j][0] - m0) + __expf(acc[i][j][1] - m0);
            s1 += __expf(acc[i][j][2] - m1) + __expf(acc[i][j][3] - m1);
        }
#pragma unroll
        for (int off = 1; off <= 2; off <<= 1) {
            float mo = __shfl_xor_sync(0xffffffffu, m0, off);
            float so = __shfl_xor_sync(0xffffffffu, s0, off);
            float Mn = fmaxf(m0, mo);
            s0 = s0 * __expf(m0 - Mn) + so * __expf(mo - Mn); m0 = Mn;
            mo = __shfl_xor_sync(0xffffffffu, m1, off);
            so = __shfl_xor_sync(0xffffffffu, s1, off);
            Mn = fmaxf(m1, mo);
            s1 = s1 * __expf(m1 - Mn) + so * __expf(mo - Mn); m1 = Mn;
        }
        if (kq == 0) {
            const int r0 = wr * 32 + i * 16 + gm;
            pm[wc][r0] = m0; ps[wc][r0] = s0;
            pm[wc][r0 + 8] = m1; ps[wc][r0 + 8] = s1;
        }
    }
    __syncthreads();
    if (tid < 128) {
        float ma = pm[0][tid], sa = ps[0][tid];
        float mb2 = pm[1][tid], sb2 = ps[1][tid];
        float M = fmaxf(ma, mb2);
        float S = sa * __expf(ma - M) + sb2 * __expf(mb2 - M);
        part[((size_t)bh * 16 + blockIdx.x) * L_ + q0 + tid] = make_float2(M, S);
    }
}

// ------ fused row-stats + streaming normalize: p = rndtf(exp(s - M) * invS) ------
// blockIdx.x = att row index (att order: hb = h*B+b). part is (b*16+h)-ordered.
__global__ __launch_bounds__(256) void normalize_fused(
    float* __restrict__ att, const float2* __restrict__ part)
{
    __shared__ float2 sh[16];
    __shared__ float2 shMS;
    const int hb = blockIdx.x >> 11, row = blockIdx.x & 2047;
    const int h = hb >> 2, b = hb & 3;        // hb = h*B_ + b, B_ = 4
    const int bh = b * 16 + h;                // part order
    const int tid = threadIdx.x;

    if (tid < 16) sh[tid] = part[((size_t)bh * 16 + tid) * L_ + row];
    __syncthreads();
    if (tid == 0) {
        float M = -INFINITY, S = 0.f;
#pragma unroll
        for (int t = 0; t < 16; t++) {
            float2 p = sh[t];
            float Mn = fmaxf(M, p.x);
            S = S * __expf(M - Mn) + p.y * __expf(p.x - Mn);
            M = Mn;
        }
        shMS = make_float2(M, 1.0f / S);
    }
    __syncthreads();
    const float2 MS = shMS;

    float4* rowp = (float4*)(att + (size_t)blockIdx.x * L_);
#pragma unroll
    for (int u = 0; u < 2; u++) {
        float4 v = rowp[u * 256 + tid];
        v.x = rndtf(__expf(v.x - MS.x) * MS.y);
        v.y = rndtf(__expf(v.y - MS.x) * MS.y);
        v.z = rndtf(__expf(v.z - MS.x) * MS.y);
        v.w = rndtf(__expf(v.w - MS.x) * MS.y);
        rowp[u * 256 + tid] = v;
    }
}

// ============ PV: AO[b,q,h,:] = P[b,h,q,:] @ Vh[2048,64] ========================
#define PTS 36
#define VTS 72
__global__ __launch_bounds__(256, 2) void pv_tf32(
    const float* __restrict__ att, const float* __restrict__ Vs,
    float* __restrict__ AO)
{
    extern __shared__ unsigned sm[];
    unsigned (*Pt)[128][PTS] = (unsigned(*)[128][PTS])sm;
    unsigned (*Vt)[32][VTS]  = (unsigned(*)[32][VTS])(sm + 2 * 128 * PTS);

    const int tid  = threadIdx.x;
    const int lane = tid & 31, warp = tid >> 5;
    const int wr = warp >> 1, wc = warp & 1;
    const int gm = lane >> 2, kq = lane & 3;
    const int bh = blockIdx.y;
    const int b = bh >> 4, h = bh & 15;
    const int q0 = blockIdx.x * 128;

    const float* Pb = att + (size_t)(h * B_ + b) * L_ * L_;
    const float* Vb = Vs + (size_t)b * L_ * HD_ + (size_t)h * DK_;
    const int prow = tid >> 1, pcb = (tid & 1) * 16;
    const int vrow = tid >> 3, vcb = (tid & 7) * 8;

    float acc[2][4][4];
#pragma unroll
    for (int i = 0; i < 2; i++)
#pragma unroll
        for (int j = 0; j < 4; j++)
#pragma unroll
            for (int r = 0; r < 4; r++) acc[i][j][r] = 0.f;

    auto load = [&](int buf, int k0) {
#pragma unroll
        for (int u = 0; u < 4; u++)
            cp16(&Pt[buf][prow][pcb + u * 4],
                 Pb + (size_t)(q0 + prow) * L_ + k0 + pcb + u * 4);
#pragma unroll
        for (int u = 0; u < 2; u++)
            cp16(&Vt[buf][vrow][vcb + u * 4],
                 Vb + (size_t)(k0 + vrow) * HD_ + vcb + u * 4);
    };

    load(0, 0); cpcommit();
    int buf = 0;
    for (int k0 = 0; k0 < L_; k0 += 32) {
        cpwait0();
        __syncthreads();
        if (k0 + 32 < L_) { load(buf ^ 1, k0 + 32); cpcommit(); }
#pragma unroll
        for (int kk = 0; kk < 32; kk += 8) {
            unsigned af[2][4], bf[4][2];
#pragma unroll
            for (int i = 0; i < 2; i++) {
                const int mb = wr * 32 + i * 16;
                af[i][0] = Pt[buf][mb + gm    ][kk + kq];
                af[i][1] = Pt[buf][mb + gm + 8][kk + kq];
                af[i][2] = Pt[buf][mb + gm    ][kk + kq + 4];
                af[i][3] = Pt[buf][mb + gm + 8][kk + kq + 4];
            }
#pragma unroll
            for (int j = 0; j < 4; j++) {
                const int nb = wc * 32 + j * 8;
                bf[j][0] = Vt[buf][kk + kq    ][nb + gm];
                bf[j][1] = Vt[buf][kk + kq + 4][nb + gm];
            }
#pragma unroll
            for (int i = 0; i < 2; i++)
#pragma unroll
                for (int j = 0; j < 4; j++) mma8(acc[i][j], af[i], bf[j]);
        }
        __syncthreads();
        buf ^= 1;
    }

#pragma unroll
    for (int i = 0; i < 2; i++)
#pragma unroll
        for (int j = 0; j < 4; j++) {
            const int q = q0 + wr * 32 + i * 16 + gm;
            const int col = wc * 32 + j * 8 + kq * 2;
            float2 o0, o1;
            o0.x = rndtf(acc[i][j][0]); o0.y = rndtf(acc[i][j][1]);
            o1.x = rndtf(acc[i][j][2]); o1.y = rndtf(acc[i][j][3]);
            *(float2*)(AO + (size_t)(b * L_ + q) * HD_ + h * DK_ + col)      = o0;
            *(float2*)(AO + (size_t)(b * L_ + q + 8) * HD_ + h * DK_ + col) = o1;
        }
}

// ---------------- residual + LayerNorm: y = LN(X + Q)*gamma + beta ---------------
__global__ __launch_bounds__(256) void ln_kernel(
    const float* __restrict__ X, const float* __restrict__ Qin,
    const float* __restrict__ gamma, const float* __restrict__ beta,
    float* __restrict__ y)
{
    __shared__ float red[8];
    const int row = blockIdx.x;
    const int tid = threadIdx.x;
    const float* xr = X + (size_t)row * DX_;
    const float* qr = Qin + (size_t)row * DX_;

    float x[4];
#pragma unroll
    for (int i = 0; i < 4; i++) x[i] = xr[tid + 256 * i] + qr[tid + 256 * i];

    float s = x[0] + x[1] + x[2] + x[3];
#pragma unroll
    for (int o = 16; o; o >>= 1) s += __shfl_xor_sync(0xffffffffu, s, o);
    if ((tid & 31) == 0) red[tid >> 5] = s;
    __syncthreads();
    s = red[0];
#pragma unroll
    for (int w = 1; w < 8; w++) s += red[w];
    const float mu = s * (1.0f / DX_);
    __syncthreads();

    float vs = 0.f;
#pragma unroll
    for (int i = 0; i < 4; i++) { float d = x[i] - mu; vs += d * d; }
#pragma unroll
    for (int o = 16; o; o >>= 1) vs += __shfl_xor_sync(0xffffffffu, vs, o);
    if ((tid & 31) == 0) red[tid >> 5] = vs;
    __syncthreads();
    vs = red[0];
#pragma unroll
    for (int w = 1; w < 8; w++) vs += red[w];
    const float var = vs * (1.0f / DX_);
    const float rs = rsqrtf(var + EPS_);

#pragma unroll
    for (int i = 0; i < 4; i++) {
        const int c = tid + 256 * i;
        y[(size_t)row * DX_ + c] = (x[i] - mu) * rs * gamma[c] + beta[c];
    }
}

// --------------------------------- launch ---------------------------------------
extern "C" void kernel_launch(void* const* d_in, const int* in_sizes, int n_in,
                              void* d_out, int out_size)
{
    const float* Q  = (const float*)d_in[0];
    const float* K  = (const float*)d_in[1];
    const float* V  = (const float*)d_in[2];
    const unsigned char* mask = (const unsigned char*)d_in[3];
    const float* Wq = (const float*)d_in[4];
    const float* bq = (const float*)d_in[5];
    const float* Wk = (const float*)d_in[6];
    const float* bk = (const float*)d_in[7];
    const float* Wv = (const float*)d_in[8];
    const float* bv = (const float*)d_in[9];
    const float* Wo = (const float*)d_in[10];
    const float* bo = (const float*)d_in[11];
    const float* gamma = (const float*)d_in[12];
    const float* beta  = (const float*)d_in[13];

    float* y   = (float*)d_out;
    float* att = (float*)d_out + (size_t)B_ * L_ * DX_;

    static float *pQs=nullptr,*pKs=nullptr,*pVs=nullptr,*pAO=nullptr,*pX=nullptr;
    static float *prWq=nullptr,*prWk=nullptr,*prWv=nullptr,*prWo=nullptr;
    static float2 *pPart=nullptr;
    static cudaStream_t s1, s2, s3;
    static cudaEvent_t evS, ev1, ev2, ev3;
    if (!pQs) {
        cudaGetSymbolAddress((void**)&pQs, g_Qs);
        cudaGetSymbolAddress((void**)&pKs, g_Ks);
        cudaGetSymbolAddress((void**)&pVs, g_Vs);
        cudaGetSymbolAddress((void**)&pAO, g_AO);
        cudaGetSymbolAddress((void**)&pX,  g_X);
        cudaGetSymbolAddress((void**)&prWq, g_rWq);
        cudaGetSymbolAddress((void**)&prWk, g_rWk);
        cudaGetSymbolAddress((void**)&prWv, g_rWv);
        cudaGetSymbolAddress((void**)&prWo, g_rWo);
        cudaGetSymbolAddress((void**)&pPart, g_part);
        cudaFuncSetAttribute(scores_tf32, cudaFuncAttributeMaxDynamicSharedMemorySize,
                             2 * 128 * SCS * 4);
        cudaFuncSetAttribute(pv_tf32, cudaFuncAttributeMaxDynamicSharedMemorySize,
                             (2 * 128 * PTS + 2 * 32 * VTS) * 4);
        cudaStreamCreateWithFlags(&s1, cudaStreamNonBlocking);
        cudaStreamCreateWithFlags(&s2, cudaStreamNonBlocking);
        cudaStreamCreateWithFlags(&s3, cudaStreamNonBlocking);
        cudaEventCreateWithFlags(&evS, cudaEventDisableTiming);
        cudaEventCreateWithFlags(&ev1, cudaEventDisableTiming);
        cudaEventCreateWithFlags(&ev2, cudaEventDisableTiming);
        cudaEventCreateWithFlags(&ev3, cudaEventDisableTiming);
    }

    const int nW = DX_ * HD_ / 4;                   // float4 count for a weight matrix
    const dim3 gProj(HD_ / 128, (B_ * L_) / 128);   // (8, 64)

    // fork
    cudaEventRecord(evS, 0);
    cudaStreamWaitEvent(s1, evS, 0);
    cudaStreamWaitEvent(s2, evS, 0);
    cudaStreamWaitEvent(s3, evS, 0);

    // s1: K chain (joins before scores)
    round_tf32<<<nW / 256, 256, 0, s1>>>((const float4*)Wk, (float4*)prWk, nW);
    sgemm_tf32<true><<<gProj, 256, 0, s1>>>(K, prWk, bk, pKs, B_ * L_, HD_, DX_);
    cudaEventRecord(ev1, s1);

    // s2: V chain (joins before pv — overlaps scores+normalize)
    round_tf32<<<nW / 256, 256, 0, s2>>>((const float4*)Wv, (float4*)prWv, nW);
    sgemm_tf32<true><<<gProj, 256, 0, s2>>>(V, prWv, bv, pVs, B_ * L_, HD_, DX_);
    cudaEventRecord(ev2, s2);

    // s3: Wo prep (joins before output projection)
    round_tf32<<<nW / 256, 256, 0, s3>>>((const float4*)Wo, (float4*)prWo, nW);
    cudaEventRecord(ev3, s3);

    // main: Q chain -> attention
    round_tf32<<<nW / 256, 256>>>((const float4*)Wq, (float4*)prWq, nW);
    sgemm_tf32<true><<<gProj, 256>>>(Q, prWq, bq, pQs, B_ * L_, HD_, DX_);

    cudaStreamWaitEvent(0, ev1, 0);
    scores_tf32<<<dim3(L_ / 128, L_ / 128, B_ * H_), 256, 2 * 128 * SCS * 4>>>(
        pQs, pKs, mask, att, pPart);
    normalize_fused<<<B_ * H_ * L_, 256>>>(att, pPart);

    cudaStreamWaitEvent(0, ev2, 0);
    pv_tf32<<<dim3(L_ / 128, B_ * H_), 256, (2 * 128 * PTS + 2 * 32 * VTS) * 4>>>(
        att, pVs, pAO);

    cudaStreamWaitEvent(0, ev3, 0);
    sgemm_tf32<false><<<gProj, 256>>>(pAO, prWo, bo, pX, B_ * L_, DX_, HD_);
    ln_kernel<<<B_ * L_, 256>>>(pX, Q, gamma, beta, y);
}

// round 12
// speedup vs baseline: 1.1305x; 1.0062x over previous
#include <cuda_runtime.h>
#include <math.h>
#include <stdint.h>

#define B_   4
#define L_   2048
#define DX_  1024
#define H_   16
#define DK_  64
#define HD_  1024      // H*DK
#define EPS_ 1e-5f

// ---------------- scratch (device globals; no allocation allowed) ----------------
__device__ float g_Qs[(size_t)B_ * L_ * HD_];
__device__ float g_Ks[(size_t)B_ * L_ * HD_];
__device__ float g_Vs[(size_t)B_ * L_ * HD_];
__device__ float g_AO[(size_t)B_ * L_ * HD_];
__device__ float g_X [(size_t)B_ * L_ * DX_];
__device__ float g_rWq[(size_t)DX_ * HD_];   // tf32-rounded weights, [K][N] layout
__device__ float g_rWk[(size_t)DX_ * HD_];
__device__ float g_rWv[(size_t)DX_ * HD_];
__device__ float g_rWo[(size_t)HD_ * DX_];
__device__ float g_part[(size_t)B_ * H_ * 16 * L_];  // (b*16+h, k-tile, row): expsum partial

// ---------------- tf32 / cp.async helpers ----------------------------------------
__device__ __forceinline__ unsigned f2tf(float x) {
    unsigned r; asm("cvt.rna.tf32.f32 %0, %1;" : "=r"(r) : "f"(x)); return r;
}
__device__ __forceinline__ float rndtf(float x) { return __uint_as_float(f2tf(x)); }

__device__ __forceinline__ void cp16(void* s, const void* g) {
    unsigned a = (unsigned)__cvta_generic_to_shared(s);
    asm volatile("cp.async.cg.shared.global [%0], [%1], 16;" :: "r"(a), "l"(g));
}
__device__ __forceinline__ void cpcommit() {
    asm volatile("cp.async.commit_group;" ::: "memory");
}
__device__ __forceinline__ void cpwait0() {
    asm volatile("cp.async.wait_group 0;" ::: "memory");
}

__device__ __forceinline__ void mma8(float* d, const unsigned* a, const unsigned* b) {
    asm volatile(
        "mma.sync.aligned.m16n8k8.row.col.f32.tf32.tf32.f32 "
        "{%0,%1,%2,%3},{%4,%5,%6,%7},{%8,%9},{%0,%1,%2,%3};"
        : "+f"(d[0]), "+f"(d[1]), "+f"(d[2]), "+f"(d[3])
        : "r"(a[0]), "r"(a[1]), "r"(a[2]), "r"(a[3]), "r"(b[0]), "r"(b[1]));
}

// ---------------- pre-round weights to tf32 --------------------------------------
__global__ __launch_bounds__(256) void round_tf32(
    const float4* __restrict__ in, float4* __restrict__ out, int n4)
{
    int i = blockIdx.x * blockDim.x + threadIdx.x;
    if (i < n4) {
        float4 v = in[i];
        v.x = rndtf(v.x); v.y = rndtf(v.y); v.z = rndtf(v.z); v.w = rndtf(v.w);
        out[i] = v;
    }
}

// ================= TF32 SGEMM: C[M,N] = A[M,K] @ B[K,N] + bias ===================
// A is RAW fp32 (rounded to tf32 in-register at fragment load); B is pre-rounded.
template<bool ROUND_OUT>
__global__ __launch_bounds__(256, 2) void sgemm_tf32(
    const float* __restrict__ A, const float* __restrict__ Bm,
    const float* __restrict__ bias, float* __restrict__ C,
    int M, int N, int K)
{
    __shared__ unsigned As[2][128][20];
    __shared__ unsigned Bs[2][16][136];
    const int tid  = threadIdx.x;
    const int lane = tid & 31, warp = tid >> 5;
    const int wr = warp >> 1, wc = warp & 1;
    const int gm = lane >> 2, kq = lane & 3;

    const float* Ab = A  + (size_t)(blockIdx.y * 128) * K;
    const float* Bb = Bm + blockIdx.x * 128;
    const int arow = tid >> 1,  acol = (tid & 1) * 8;
    const int brow = tid >> 4,  bcol = (tid & 15) * 8;

    float acc[2][8][4];
#pragma unroll
    for (int i = 0; i < 2; i++)
#pragma unroll
        for (int j = 0; j < 8; j++)
#pragma unroll
            for (int r = 0; r < 4; r++) acc[i][j][r] = 0.f;

    auto load = [&](int buf, int k0) {
        cp16(&As[buf][arow][acol],     Ab + (size_t)arow * K + k0 + acol);
        cp16(&As[buf][arow][acol + 4], Ab + (size_t)arow * K + k0 + acol + 4);
        cp16(&Bs[buf][brow][bcol],     Bb + (size_t)(k0 + brow) * N + bcol);
        cp16(&Bs[buf][brow][bcol + 4], Bb + (size_t)(k0 + brow) * N + bcol + 4);
    };

    load(0, 0); cpcommit();
    int buf = 0;
    for (int k0 = 0; k0 < K; k0 += 16) {
        cpwait0();
        __syncthreads();
        if (k0 + 16 < K) { load(buf ^ 1, k0 + 16); cpcommit(); }
#pragma unroll
        for (int kk = 0; kk < 16; kk += 8) {
            unsigned af[2][4], bf[8][2];
#pragma unroll
            for (int i = 0; i < 2; i++) {
                const int mb = wr * 32 + i * 16;
                af[i][0] = f2tf(__uint_as_float(As[buf][mb + gm    ][kk + kq]));
                af[i][1] = f2tf(__uint_as_float(As[buf][mb + gm + 8][kk + kq]));
                af[i][2] = f2tf(__uint_as_float(As[buf][mb + gm    ][kk + kq + 4]));
                af[i][3] = f2tf(__uint_as_float(As[buf][mb + gm + 8][kk + kq + 4]));
            }
#pragma unroll
            for (int j = 0; j < 8; j++) {
                const int nb = wc * 64 + j * 8;
                bf[j][0] = Bs[buf][kk + kq    ][nb + gm];
                bf[j][1] = Bs[buf][kk + kq + 4][nb + gm];
            }
#pragma unroll
            for (int i = 0; i < 2; i++)
#pragma unroll
                for (int j = 0; j < 8; j++) mma8(acc[i][j], af[i], bf[j]);
        }
        __syncthreads();
        buf ^= 1;
    }

#pragma unroll
    for (int i = 0; i < 2; i++)
#pragma unroll
        for (int j = 0; j < 8; j++) {
            const int row = blockIdx.y * 128 + wr * 32 + i * 16 + gm;
            const int col = blockIdx.x * 128 + wc * 64 + j * 8 + kq * 2;
            float2 bv = *(const float2*)(bias + col);
            float2 o0, o1;
            o0.x = acc[i][j][0] + bv.x; o0.y = acc[i][j][1] + bv.y;
            o1.x = acc[i][j][2] + bv.x; o1.y = acc[i][j][3] + bv.y;
            if (ROUND_OUT) {
                o0.x = rndtf(o0.x); o0.y = rndtf(o0.y);
                o1.x = rndtf(o1.x); o1.y = rndtf(o1.y);
            }
            *(float2*)(C + (size_t)row * N + col)       = o0;
            *(float2*)(C + (size_t)(row + 8) * N + col) = o1;
        }
}

// ===== scores: e = exp((Qh@Kh^T)/8) masked->0; writes e + per-tile row expsums ====
#define SCS 68
__global__ __launch_bounds__(256, 2) void scores_tf32(
    const float* __restrict__ Qs, const float* __restrict__ Ks,
    const unsigned char* __restrict__ mask, float* __restrict__ att,
    float* __restrict__ part)
{
    extern __shared__ unsigned sm[];
    unsigned (*Qt)[SCS] = (unsigned(*)[SCS])sm;
    unsigned (*Kt)[SCS] = (unsigned(*)[SCS])(sm + 128 * SCS);
    unsigned char* msk = (unsigned char*)sm;     // reused after mainloop
    __shared__ float ps[2][128];

    const int tid  = threadIdx.x;
    const int lane = tid & 31, warp = tid >> 5;
    const int wr = warp >> 1, wc = warp & 1;
    const int gm = lane >> 2, kq = lane & 3;
    const int bh = blockIdx.z;                  // b*16 + h
    const int b = bh >> 4, h = bh & 15;
    const int q0 = blockIdx.y * 128, n0 = blockIdx.x * 128;

    const float* Qb = Qs + (size_t)b * L_ * HD_ + (size_t)h * DK_;
    const float* Kb = Ks + (size_t)b * L_ * HD_ + (size_t)h * DK_;
    const int lrow = tid >> 1, lcb = (tid & 1) * 32;

#pragma unroll
    for (int u = 0; u < 8; u++) {
        cp16(&Qt[lrow][lcb + u * 4], Qb + (size_t)(q0 + lrow) * HD_ + lcb + u * 4);
        cp16(&Kt[lrow][lcb + u * 4], Kb + (size_t)(n0 + lrow) * HD_ + lcb + u * 4);
    }
    cpcommit();

    float acc[2][8][4];
#pragma unroll
    for (int i = 0; i < 2; i++)
#pragma unroll
        for (int j = 0; j < 8; j++)
#pragma unroll
            for (int r = 0; r < 4; r++) acc[i][j][r] = 0.f;

    cpwait0();
    __syncthreads();

#pragma unroll
    for (int kk = 0; kk < 64; kk += 8) {
        unsigned af[2][4], bf[8][2];
#pragma unroll
        for (int i = 0; i < 2; i++) {
            const int mb = wr * 32 + i * 16;
            af[i][0] = Qt[mb + gm    ][kk + kq];
            af[i][1] = Qt[mb + gm + 8][kk + kq];
            af[i][2] = Qt[mb + gm    ][kk + kq + 4];
            af[i][3] = Qt[mb + gm + 8][kk + kq + 4];
        }
#pragma unroll
        for (int j = 0; j < 8; j++) {
            const int nb = wc * 64 + j * 8;
            bf[j][0] = Kt[nb + gm][kk + kq];
            bf[j][1] = Kt[nb + gm][kk + kq + 4];
        }
#pragma unroll
        for (int i = 0; i < 2; i++)
#pragma unroll
            for (int j = 0; j < 8; j++) mma8(acc[i][j], af[i], bf[j]);
    }

    // stage mask tile into smem (Qt/Kt dead now) with coalesced 16B loads
    __syncthreads();
    {
        const unsigned char* mg = mask + (size_t)b * L_ * L_
                                 + (size_t)(q0 + (tid >> 1)) * L_ + n0 + (tid & 1) * 64;
        unsigned char* msrow = msk + (tid >> 1) * 128 + (tid & 1) * 64;
#pragma unroll
        for (int u = 0; u < 4; u++)
            cp16(msrow + u * 16, mg + u * 16);
    }
    cpcommit(); cpwait0();
    __syncthreads();

    float* outb = att + (size_t)(h * B_ + b) * L_ * L_;

    // e = exp(s/8) (masked -> 0), write raw e, keep in acc for row sums
#pragma unroll
    for (int i = 0; i < 2; i++)
#pragma unroll
        for (int j = 0; j < 8; j++) {
            const int ql = wr * 32 + i * 16 + gm;
            const int kl = wc * 64 + j * 8 + kq * 2;
            acc[i][j][0] = msk[ql * 128 + kl]           ? 0.f : __expf(acc[i][j][0] * 0.125f);
            acc[i][j][1] = msk[ql * 128 + kl + 1]       ? 0.f : __expf(acc[i][j][1] * 0.125f);
            acc[i][j][2] = msk[(ql + 8) * 128 + kl]     ? 0.f : __expf(acc[i][j][2] * 0.125f);
            acc[i][j][3] = msk[(ql + 8) * 128 + kl + 1] ? 0.f : __expf(acc[i][j][3] * 0.125f);
            *(float2*)(outb + (size_t)(q0 + ql) * L_ + n0 + kl) =
                make_float2(acc[i][j][0], acc[i][j][1]);
            *(float2*)(outb + (size_t)(q0 + ql + 8) * L_ + n0 + kl) =
                make_float2(acc[i][j][2], acc[i][j][3]);
        }

    // per-tile row expsums: per-thread, quad shuffle, cross-warp-col combine
#pragma unroll
    for (int i = 0; i < 2; i++) {
        float s0 = 0.f, s1 = 0.f;
#pragma unroll
        for (int j = 0; j < 8; j++) {
            s0 += acc[i][j][0] + acc[i][j][1];
            s1 += acc[i][j][2] + acc[i][j][3];
        }
#pragma unroll
        for (int off = 1; off <= 2; off <<= 1) {
            s0 += __shfl_xor_sync(0xffffffffu, s0, off);
            s1 += __shfl_xor_sync(0xffffffffu, s1, off);
        }
        if (kq == 0) {
            const int r0 = wr * 32 + i * 16 + gm;
            ps[wc][r0] = s0;
            ps[wc][r0 + 8] = s1;
        }
    }
    __syncthreads();
    if (tid < 128)
        part[((size_t)bh * 16 + blockIdx.x) * L_ + q0 + tid] = ps[0][tid] + ps[1][tid];
}

// ====== fused PV: invS from partials; p = rndtf(e*invS) -> att + smem; AO = p@V ===
#define PTS 36
#define VTS 72
__global__ __launch_bounds__(256, 2) void pv_tf32(
    float* __restrict__ att, const float* __restrict__ Vs,
    const float* __restrict__ part, float* __restrict__ AO)
{
    extern __shared__ unsigned sm[];
    unsigned (*Pt)[128][PTS] = (unsigned(*)[128][PTS])sm;
    unsigned (*Vt)[32][VTS]  = (unsigned(*)[32][VTS])(sm + 2 * 128 * PTS);
    __shared__ float sInv[128];

    const int tid  = threadIdx.x;
    const int lane = tid & 31, warp = tid >> 5;
    const int wr = warp >> 1, wc = warp & 1;
    const int gm = lane >> 2, kq = lane & 3;
    const int bh = blockIdx.y;                  // b*16 + h
    const int b = bh >> 4, h = bh & 15;
    const int q0 = blockIdx.x * 128;

    float* Pb = att + (size_t)(h * B_ + b) * L_ * L_;
    const float* Vb = Vs + (size_t)b * L_ * HD_ + (size_t)h * DK_;
    const int prow = tid >> 1, pcb = (tid & 1) * 16;
    const int vrow = tid >> 3, vcb = (tid & 7) * 8;

    float acc[2][4][4];
#pragma unroll
    for (int i = 0; i < 2; i++)
#pragma unroll
        for (int j = 0; j < 4; j++)
#pragma unroll
            for (int r = 0; r < 4; r++) acc[i][j][r] = 0.f;

    auto load = [&](int buf, int k0) {
#pragma unroll
        for (int u = 0; u < 4; u++)
            cp16(&Pt[buf][prow][pcb + u * 4],
                 Pb + (size_t)(q0 + prow) * L_ + k0 + pcb + u * 4);
#pragma unroll
        for (int u = 0; u < 2; u++)
            cp16(&Vt[buf][vrow][vcb + u * 4],
                 Vb + (size_t)(k0 + vrow) * HD_ + vcb + u * 4);
    };

    load(0, 0); cpcommit();

    // prologue: per-row invS from the 16 per-tile partial expsums
    if (tid < 128) {
        float s = 0.f;
#pragma unroll
        for (int t = 0; t < 16; t++)
            s += part[((size_t)bh * 16 + t) * L_ + q0 + tid];
        sInv[tid] = 1.0f / s;
    }

    int buf = 0;
    for (int k0 = 0; k0 < L_; k0 += 32) {
        cpwait0();
        __syncthreads();
        if (k0 + 32 < L_) { load(buf ^ 1, k0 + 32); cpcommit(); }

        // scale e -> p (RNA-rounded), store back to smem AND to att (final output)
        {
            const float inv = sInv[prow];
            float* psm = (float*)&Pt[buf][prow][pcb];
            float* pgm = Pb + (size_t)(q0 + prow) * L_ + k0 + pcb;
#pragma unroll
            for (int u = 0; u < 4; u++) {
                float4 v = *(float4*)(psm + u * 4);
                v.x = rndtf(v.x * inv);
                v.y = rndtf(v.y * inv);
                v.z = rndtf(v.z * inv);
                v.w = rndtf(v.w * inv);
                *(float4*)(psm + u * 4) = v;
                *(float4*)(pgm + u * 4) = v;
            }
        }
        __syncthreads();

#pragma unroll
        for (int kk = 0; kk < 32; kk += 8) {
            unsigned af[2][4], bf[4][2];
#pragma unroll
            for (int i = 0; i < 2; i++) {
                const int mb = wr * 32 + i * 16;
                af[i][0] = Pt[buf][mb + gm    ][kk + kq];
                af[i][1] = Pt[buf][mb + gm + 8][kk + kq];
                af[i][2] = Pt[buf][mb + gm    ][kk + kq + 4];
                af[i][3] = Pt[buf][mb + gm + 8][kk + kq + 4];
            }
#pragma unroll
            for (int j = 0; j < 4; j++) {
                const int nb = wc * 32 + j * 8;
                bf[j][0] = Vt[buf][kk + kq    ][nb + gm];
                bf[j][1] = Vt[buf][kk + kq + 4][nb + gm];
            }
#pragma unroll
            for (int i = 0; i < 2; i++)
#pragma unroll
                for (int j = 0; j < 4; j++) mma8(acc[i][j], af[i], bf[j]);
        }
        __syncthreads();
        buf ^= 1;
    }

#pragma unroll
    for (int i = 0; i < 2; i++)
#pragma unroll
        for (int j = 0; j < 4; j++) {
            const int q = q0 + wr * 32 + i * 16 + gm;
            const int col = wc * 32 + j * 8 + kq * 2;
            float2 o0, o1;
            o0.x = rndtf(acc[i][j][0]); o0.y = rndtf(acc[i][j][1]);
            o1.x = rndtf(acc[i][j][2]); o1.y = rndtf(acc[i][j][3]);
            *(float2*)(AO + (size_t)(b * L_ + q) * HD_ + h * DK_ + col)      = o0;
            *(float2*)(AO + (size_t)(b * L_ + q + 8) * HD_ + h * DK_ + col) = o1;
        }
}

// ---------------- residual + LayerNorm: y = LN(X + Q)*gamma + beta ---------------
__global__ __launch_bounds__(256) void ln_kernel(
    const float* __restrict__ X, const float* __restrict__ Qin,
    const float* __restrict__ gamma, const float* __restrict__ beta,
    float* __restrict__ y)
{
    __shared__ float red[8];
    const int row = blockIdx.x;
    const int tid = threadIdx.x;
    const float* xr = X + (size_t)row * DX_;
    const float* qr = Qin + (size_t)row * DX_;

    float x[4];
#pragma unroll
    for (int i = 0; i < 4; i++) x[i] = xr[tid + 256 * i] + qr[tid + 256 * i];

    float s = x[0] + x[1] + x[2] + x[3];
#pragma unroll
    for (int o = 16; o; o >>= 1) s += __shfl_xor_sync(0xffffffffu, s, o);
    if ((tid & 31) == 0) red[tid >> 5] = s;
    __syncthreads();
    s = red[0];
#pragma unroll
    for (int w = 1; w < 8; w++) s += red[w];
    const float mu = s * (1.0f / DX_);
    __syncthreads();

    float vs = 0.f;
#pragma unroll
    for (int i = 0; i < 4; i++) { float d = x[i] - mu; vs += d * d; }
#pragma unroll
    for (int o = 16; o; o >>= 1) vs += __shfl_xor_sync(0xffffffffu, vs, o);
    if ((tid & 31) == 0) red[tid >> 5] = vs;
    __syncthreads();
    vs = red[0];
#pragma unroll
    for (int w = 1; w < 8; w++) vs += red[w];
    const float var = vs * (1.0f / DX_);
    const float rs = rsqrtf(var + EPS_);

#pragma unroll
    for (int i = 0; i < 4; i++) {
        const int c = tid + 256 * i;
        y[(size_t)row * DX_ + c] = (x[i] - mu) * rs * gamma[c] + beta[c];
    }
}

// --------------------------------- launch ---------------------------------------
extern "C" void kernel_launch(void* const* d_in, const int* in_sizes, int n_in,
                              void* d_out, int out_size)
{
    const float* Q  = (const float*)d_in[0];
    const float* K  = (const float*)d_in[1];
    const float* V  = (const float*)d_in[2];
    const unsigned char* mask = (const unsigned char*)d_in[3];
    const float* Wq = (const float*)d_in[4];
    const float* bq = (const float*)d_in[5];
    const float* Wk = (const float*)d_in[6];
    const float* bk = (const float*)d_in[7];
    const float* Wv = (const float*)d_in[8];
    const float* bv = (const float*)d_in[9];
    const float* Wo = (const float*)d_in[10];
    const float* bo = (const float*)d_in[11];
    const float* gamma = (const float*)d_in[12];
    const float* beta  = (const float*)d_in[13];

    float* y   = (float*)d_out;
    float* att = (float*)d_out + (size_t)B_ * L_ * DX_;

    static float *pQs=nullptr,*pKs=nullptr,*pVs=nullptr,*pAO=nullptr,*pX=nullptr;
    static float *prWq=nullptr,*prWk=nullptr,*prWv=nullptr,*prWo=nullptr;
    static float *pPart=nullptr;
    static cudaStream_t s1, s2, s3;
    static cudaEvent_t evS, ev1, ev2, ev3;
    if (!pQs) {
        cudaGetSymbolAddress((void**)&pQs, g_Qs);
        cudaGetSymbolAddress((void**)&pKs, g_Ks);
        cudaGetSymbolAddress((void**)&pVs, g_Vs);
        cudaGetSymbolAddress((void**)&pAO, g_AO);
        cudaGetSymbolAddress((void**)&pX,  g_X);
        cudaGetSymbolAddress((void**)&prWq, g_rWq);
        cudaGetSymbolAddress((void**)&prWk, g_rWk);
        cudaGetSymbolAddress((void**)&prWv, g_rWv);
        cudaGetSymbolAddress((void**)&prWo, g_rWo);
        cudaGetSymbolAddress((void**)&pPart, g_part);
        cudaFuncSetAttribute(scores_tf32, cudaFuncAttributeMaxDynamicSharedMemorySize,
                             2 * 128 * SCS * 4);
        cudaFuncSetAttribute(pv_tf32, cudaFuncAttributeMaxDynamicSharedMemorySize,
                             (2 * 128 * PTS + 2 * 32 * VTS) * 4);
        cudaStreamCreateWithFlags(&s1, cudaStreamNonBlocking);
        cudaStreamCreateWithFlags(&s2, cudaStreamNonBlocking);
        cudaStreamCreateWithFlags(&s3, cudaStreamNonBlocking);
        cudaEventCreateWithFlags(&evS, cudaEventDisableTiming);
        cudaEventCreateWithFlags(&ev1, cudaEventDisableTiming);
        cudaEventCreateWithFlags(&ev2, cudaEventDisableTiming);
        cudaEventCreateWithFlags(&ev3, cudaEventDisableTiming);
    }

    const int nW = DX_ * HD_ / 4;                   // float4 count for a weight matrix
    const dim3 gProj(HD_ / 128, (B_ * L_) / 128);   // (8, 64)

    // fork
    cudaEventRecord(evS, 0);
    cudaStreamWaitEvent(s1, evS, 0);
    cudaStreamWaitEvent(s2, evS, 0);
    cudaStreamWaitEvent(s3, evS, 0);

    // s1: K chain (joins before scores)
    round_tf32<<<nW / 256, 256, 0, s1>>>((const float4*)Wk, (float4*)prWk, nW);
    sgemm_tf32<true><<<gProj, 256, 0, s1>>>(K, prWk, bk, pKs, B_ * L_, HD_, DX_);
    cudaEventRecord(ev1, s1);

    // s2: V chain (joins before pv — overlaps scores)
    round_tf32<<<nW / 256, 256, 0, s2>>>((const float4*)Wv, (float4*)prWv, nW);
    sgemm_tf32<true><<<gProj, 256, 0, s2>>>(V, prWv, bv, pVs, B_ * L_, HD_, DX_);
    cudaEventRecord(ev2, s2);

    // s3: Wo prep (joins before output projection)
    round_tf32<<<nW / 256, 256, 0, s3>>>((const float4*)Wo, (float4*)prWo, nW);
    cudaEventRecord(ev3, s3);

    // main: Q chain -> attention
    round_tf32<<<nW / 256, 256>>>((const float4*)Wq, (float4*)prWq, nW);
    sgemm_tf32<true><<<gProj, 256>>>(Q, prWq, bq, pQs, B_ * L_, HD_, DX_);

    cudaStreamWaitEvent(0, ev1, 0);
    scores_tf32<<<dim3(L_ / 128, L_ / 128, B_ * H_), 256, 2 * 128 * SCS * 4>>>(
        pQs, pKs, mask, att, pPart);

    cudaStreamWaitEvent(0, ev2, 0);
    pv_tf32<<<dim3(L_ / 128, B_ * H_), 256, (2 * 128 * PTS + 2 * 32 * VTS) * 4>>>(
        att, pVs, pPart, pAO);

    cudaStreamWaitEvent(0, ev3, 0);
    sgemm_tf32<false><<<gProj, 256>>>(pAO, prWo, bo, pX, B_ * L_, DX_, HD_);
    ln_kernel<<<B_ * L_, 256>>>(pX, Q, gamma, beta, y);
}